// round 16
// baseline (speedup 1.0000x reference)
#include <cuda_runtime.h>
#include <cuda_fp16.h>

#define NX 256
#define NY 256
#define NZ 256
#define DETU 128
#define DETV 128
#define NVIEWS 8
#define NSTEPS 192

// Padded packed volume: pad 8 voxels low / 8 high in every dim.
#define PXD 272
#define PYD 272
#define PZD 272
#define U4  (PZD / 4)              // uint4 per z-row = 68
#define PLANE_U4 (PYD * U4)

// g_pairP[(xi*PYD+yi)*PZD+zi] = ( half(v[zi-8]), half(v[zi-7]) ); zeros in pads
__device__ __half2 g_pairP[PXD * PYD * PZD];   // 80.5 MB

#define MAIN_BLOCKS ((NX * NY * NZ / 4) / 256)            // 16384
#define NBORDER_U4 (16 * PLANE_U4 + 16 * 256 * U4)
#define BORDER_BLOCKS ((NBORDER_U4 + 255) / 256)

#define PAD_SHIFT ((8 * PYD + 8) * PZD + 8)

// ---------------------------------------------------------------------------
// Kernel A1: padded z-pair volume fill (+ border zeroing). NO relu write —
// relu is produced concurrently with proj on a side stream.
// ---------------------------------------------------------------------------
__global__ void vol_pack_kernel(const float* __restrict__ x,
                                const float* __restrict__ r) {
    if (blockIdx.x >= MAIN_BLOCKS) {
        int idx = (blockIdx.x - MAIN_BLOCKS) * blockDim.x + threadIdx.x;
        uint4 z4 = make_uint4(0, 0, 0, 0);
        if (idx < 16 * PLANE_U4) {
            int p = idx / PLANE_U4;
            int rem = idx - p * PLANE_U4;
            int xi = (p < 8) ? p : (256 + p);
            ((uint4*)g_pairP)[xi * PLANE_U4 + rem] = z4;
        } else if (idx < NBORDER_U4) {
            int j = idx - 16 * PLANE_U4;
            int p = j / (256 * U4);
            int rem = j - p * (256 * U4);
            int yi = (p < 8) ? p : (256 + p);
            int xi = 8 + rem / U4;
            int zz = rem - (rem / U4) * U4;
            ((uint4*)g_pairP)[(xi * PYD + yi) * U4 + zz] = z4;
        }
        return;
    }

    int i = blockIdx.x * blockDim.x + threadIdx.x;   // float4 index
    const float4* x4 = (const float4*)x;
    const float4* r4 = (const float4*)r;
    float4 a = x4[i];
    float4 b = r4[i];
    float4 s;
    s.x = a.x + b.x; s.y = a.y + b.y; s.z = a.z + b.z; s.w = a.w + b.w;

    int base = i * 4;
    int t = i & 63;              // z-chunk index within row (z = 4t)
    int row = i >> 6;            // x*256 + y
    int xi = (row >> 8) + 8;
    int yi = (row & 255) + 8;

    float s4 = 0.0f;
    if (t < 63) s4 = x[base + 4] + r[base + 4];   // neighbor line: L1/L2 hit

    uint4* rowp4 = (uint4*)(g_pairP + (xi * PYD + yi) * PZD);

    // pair[zi=4t+8+j] = (v[4t+j], v[4t+j+1]) -> uint4 index t+2
    union { __half2 h[4]; uint4 u; } pk;
    pk.h[0] = __floats2half2_rn(s.x, s.y);
    pk.h[1] = __floats2half2_rn(s.y, s.z);
    pk.h[2] = __floats2half2_rn(s.z, s.w);
    pk.h[3] = __floats2half2_rn(s.w, s4);
    rowp4[t + 2] = pk.u;

    if (t == 0) {
        union { __half2 h[4]; uint4 u; } lo;
        lo.h[0] = __floats2half2_rn(0.0f, 0.0f);
        lo.h[1] = lo.h[0];
        lo.h[2] = lo.h[0];
        lo.h[3] = __floats2half2_rn(0.0f, s.x);   // (v[-1], v[0])
        rowp4[0] = make_uint4(0, 0, 0, 0);
        rowp4[1] = lo.u;
    }
    if (t == 63) {
        rowp4[66] = make_uint4(0, 0, 0, 0);
        rowp4[67] = make_uint4(0, 0, 0, 0);
    }
}

// ---------------------------------------------------------------------------
// Kernel A2: relu from the lo halves of the pair array (runs concurrently
// with proj; reads proj's own L2-warm data, streams the write out).
// relu_out[z] = max( (float)pair[z+8].lo , 0 )  —  pair.lo = half(v[z])
// ---------------------------------------------------------------------------
__global__ void relu_kernel(float* __restrict__ relu_out) {
    int i = blockIdx.x * blockDim.x + threadIdx.x;   // float4 index
    int t = i & 63;
    int row = i >> 6;
    int xi = (row >> 8) + 8;
    int yi = (row & 255) + 8;

    const uint4* rowp4 = (const uint4*)(g_pairP + (xi * PYD + yi) * PZD);
    uint4 p = rowp4[t + 2];                          // pairs zi=4t+8..4t+11

    float4 o;
    o.x = fmaxf(__half2float(__ushort_as_half((unsigned short)(p.x & 0xFFFF))), 0.0f);
    o.y = fmaxf(__half2float(__ushort_as_half((unsigned short)(p.y & 0xFFFF))), 0.0f);
    o.z = fmaxf(__half2float(__ushort_as_half((unsigned short)(p.z & 0xFFFF))), 0.0f);
    o.w = fmaxf(__half2float(__ushort_as_half((unsigned short)(p.w & 0xFFFF))), 0.0f);
    __stcs((float4*)relu_out + i, o);
}

// ---------------------------------------------------------------------------
// half2 SIMD bilinear blend, fp32 z-lerp
// ---------------------------------------------------------------------------
__device__ __forceinline__ float tri_blend(__half2 A, __half2 B, __half2 C, __half2 D,
                                           float fx, float fy, float fz) {
    float gx = 1.0f - fx, gy = 1.0f - fy;
    __half2 w00 = __float2half2_rn(gx * gy);
    __half2 w01 = __float2half2_rn(gx * fy);
    __half2 w10 = __float2half2_rn(fx * gy);
    __half2 w11 = __float2half2_rn(fx * fy);
    __half2 P = __hmul2(A, w00);
    P = __hfma2(B, w01, P);
    P = __hfma2(C, w10, P);
    P = __hfma2(D, w11, P);
    float2 p = __half22float2(P);
    return p.x * (1.0f - fz) + p.y * fz;
}

// Single sample (tail): clamp-free, 8-voxel pad absorbs overshoot
__device__ __forceinline__ float trilin_nc(float px, float py, float pz) {
    float xf = floorf(px), yf = floorf(py), zf = floorf(pz);
    float fx = px - xf, fy = py - yf, fz = pz - zf;
    int off = (((int)xf * PYD + (int)yf) * PZD + (int)zf) + PAD_SHIFT;
    const __half2* q = g_pairP + off;
    return tri_blend(__ldg(q), __ldg(q + PZD),
                     __ldg(q + PYD * PZD), __ldg(q + PYD * PZD + PZD),
                     fx, fy, fz);
}

__device__ __forceinline__ void slab_clip(float p0, float dd, float lo, float hi,
                                          float& t0, float& t1) {
    if (fabsf(dd) > 1e-9f) {
        float r = 1.0f / dd;
        float ta = (lo - p0) * r, tb = (hi - p0) * r;
        t0 = fmaxf(t0, fminf(ta, tb));
        t1 = fminf(t1, fmaxf(ta, tb));
    } else if (p0 <= lo || p0 >= hi) {
        t1 = -1e9f;
    }
}

// ---------------------------------------------------------------------------
// Kernel B: cone-beam forward projection — single-wave, full ray per thread
// ---------------------------------------------------------------------------
__global__ void __launch_bounds__(128, 8)
proj_kernel(const float* __restrict__ src_pos,
            const float* __restrict__ det_center,
            const float* __restrict__ det_u_vec,
            const float* __restrict__ det_v_vec,
            const float* __restrict__ pdu,
            const float* __restrict__ pdv,
            const float* __restrict__ psp,
            float* __restrict__ sino) {
    const int v = threadIdx.x;
    const int u = blockIdx.x;
    const int view = blockIdx.y;

    const float du = __ldg(pdu);
    const float dv = __ldg(pdv);
    const float inv_sp = 1.0f / __ldg(psp);

    const float sx = __ldg(&src_pos[view * 3 + 0]);
    const float sy = __ldg(&src_pos[view * 3 + 1]);
    const float sz = __ldg(&src_pos[view * 3 + 2]);
    const float ccx = __ldg(&det_center[view * 3 + 0]);
    const float ccy = __ldg(&det_center[view * 3 + 1]);
    const float ccz = __ldg(&det_center[view * 3 + 2]);
    const float ux = __ldg(&det_u_vec[view * 3 + 0]);
    const float uy = __ldg(&det_u_vec[view * 3 + 1]);
    const float uz = __ldg(&det_u_vec[view * 3 + 2]);
    const float vx = __ldg(&det_v_vec[view * 3 + 0]);
    const float vy = __ldg(&det_v_vec[view * 3 + 1]);
    const float vz = __ldg(&det_v_vec[view * 3 + 2]);

    const float uu = ((float)u - (float)(DETU - 1) * 0.5f) * du;
    const float vv = ((float)v - (float)(DETV - 1) * 0.5f) * dv;

    const float dx = (ccx + uu * ux + vv * vx) - sx;
    const float dy = (ccy + uu * uy + vv * vy) - sy;
    const float dz = (ccz + uu * uz + vv * vz) - sz;
    const float ray_len = sqrtf(dx * dx + dy * dy + dz * dz);

    const float cx = (float)(NX - 1) * 0.5f;
    const float cy = (float)(NY - 1) * 0.5f;
    const float cz = (float)(NZ - 1) * 0.5f;
    const float p0x = fmaf(sx, inv_sp, cx);
    const float p0y = fmaf(sy, inv_sp, cy);
    const float p0z = fmaf(sz, inv_sp, cz);
    const float ddx = dx * inv_sp;
    const float ddy = dy * inv_sp;
    const float ddz = dz * inv_sp;

    float t0 = 0.0f, t1 = 1.0f;
    slab_clip(p0x, ddx, -1.0f, (float)NX, t0, t1);
    slab_clip(p0y, ddy, -1.0f, (float)NY, t0, t1);
    slab_clip(p0z, ddz, -1.0f, (float)NZ, t0, t1);

    int k0 = 0, k1 = -1;
    if (t1 > t0) {
        k0 = max((int)ceilf(t0 * (float)NSTEPS - 0.5f) - 1, 0);
        k1 = min((int)floorf(t1 * (float)NSTEPS - 0.5f) + 1, NSTEPS - 1);
    }

    const float inv_n = 1.0f / (float)NSTEPS;
    const float ddnx = ddx * inv_n, ddny = ddy * inv_n, ddnz = ddz * inv_n;
    const float bx = fmaf(0.5f, ddnx, p0x);
    const float by = fmaf(0.5f, ddny, p0y);
    const float bz = fmaf(0.5f, ddnz, p0z);

    float acc = 0.0f;
    int kk = k0;

#define PREP(i, KF)                                                            \
    float px##i = fmaf((KF), ddnx, bx);                                        \
    float py##i = fmaf((KF), ddny, by);                                        \
    float pz##i = fmaf((KF), ddnz, bz);                                        \
    float xf##i = floorf(px##i), yf##i = floorf(py##i), zf##i = floorf(pz##i); \
    float fx##i = px##i - xf##i, fy##i = py##i - yf##i, fz##i = pz##i - zf##i; \
    int off##i = (((int)xf##i * PYD + (int)yf##i) * PZD + (int)zf##i) + PAD_SHIFT;

#define LOADS(i)                                                               \
    __half2 A##i = __ldg(g_pairP + off##i);                                    \
    __half2 B##i = __ldg(g_pairP + off##i + PZD);                              \
    __half2 C##i = __ldg(g_pairP + off##i + PYD * PZD);                        \
    __half2 D##i = __ldg(g_pairP + off##i + PYD * PZD + PZD);

    for (; kk + 3 <= k1; kk += 4) {
        PREP(0, (float)kk)
        PREP(1, (float)(kk + 1))
        PREP(2, (float)(kk + 2))
        PREP(3, (float)(kk + 3))

        LOADS(0) LOADS(1) LOADS(2) LOADS(3)

        acc += tri_blend(A0, B0, C0, D0, fx0, fy0, fz0);
        acc += tri_blend(A1, B1, C1, D1, fx1, fy1, fz1);
        acc += tri_blend(A2, B2, C2, D2, fx2, fy2, fz2);
        acc += tri_blend(A3, B3, C3, D3, fx3, fy3, fz3);
    }
    for (; kk <= k1; ++kk) {
        float kf = (float)kk;
        acc += trilin_nc(fmaf(kf, ddnx, bx), fmaf(kf, ddny, by), fmaf(kf, ddnz, bz));
    }
#undef PREP
#undef LOADS

    sino[(view * DETU + u) * DETV + v] = acc * (ray_len * inv_n);
}

// ---------------------------------------------------------------------------
// Launch: vol_pack -> fork { proj (main) || relu (side stream) } -> join.
// Statics initialize on the uncaptured correctness call; event edges are
// baked into the captured graph as dependencies.
// ---------------------------------------------------------------------------
extern "C" void kernel_launch(void* const* d_in, const int* in_sizes, int n_in,
                              void* d_out, int out_size) {
    const float* x    = (const float*)d_in[0];
    const float* reco = (const float*)d_in[1];
    const float* src  = (const float*)d_in[2];
    const float* dc   = (const float*)d_in[3];
    const float* duv  = (const float*)d_in[4];
    const float* dvv  = (const float*)d_in[5];
    const float* pdu  = (const float*)d_in[6];
    const float* pdv  = (const float*)d_in[7];
    const float* psp  = (const float*)d_in[8];

    float* out  = (float*)d_out;
    float* sino = out;                                   // [8,128,128]
    float* relu = out + NVIEWS * DETU * DETV;            // [256^3]

    static cudaStream_t s2 = nullptr;
    static cudaEvent_t ev_vol = nullptr, ev_relu = nullptr;
    if (!s2) {
        cudaStreamCreateWithFlags(&s2, cudaStreamNonBlocking);
        cudaEventCreateWithFlags(&ev_vol, cudaEventDisableTiming);
        cudaEventCreateWithFlags(&ev_relu, cudaEventDisableTiming);
    }

    // main stream: pair-volume build (no relu)
    vol_pack_kernel<<<MAIN_BLOCKS + BORDER_BLOCKS, 256>>>(x, reco);
    cudaEventRecord(ev_vol, 0);

    // side stream: relu from pair los, concurrent with proj
    cudaStreamWaitEvent(s2, ev_vol, 0);
    relu_kernel<<<MAIN_BLOCKS, 256, 0, s2>>>(relu);
    cudaEventRecord(ev_relu, s2);

    // main stream: projection
    dim3 grid(DETU, NVIEWS);
    proj_kernel<<<grid, 128>>>(src, dc, duv, dvv, pdu, pdv, psp, sino);

    // join
    cudaStreamWaitEvent(0, ev_relu, 0);
}

// round 17
// speedup vs baseline: 1.4568x; 1.4568x over previous
#include <cuda_runtime.h>
#include <cuda_fp16.h>

#define NX 256
#define NY 256
#define NZ 256
#define DETU 128
#define DETV 128
#define NVIEWS 8
#define NSTEPS 192

// Padded packed volume dims: voxel (x,y,z), x0 in [-1,257] -> xi = x0+1 in [0,258]
#define PXD 259
#define PYD 259
#define PZD 260   // z-stride padded to multiple of 4 for aligned uint4 row stores

// g_pairP[(xi*PYD + yi)*PZD + zi] = ( half(v[zi-1]), half(v[zi]) ), zeros in pads
__device__ __half2 g_pairP[PXD * PYD * PZD];   // ~69.8 MB

#define MAIN_BLOCKS ((NX * NY * NZ / 4) / 256)          // 16384
#define NBORDER (3 * PYD * PZD + 3 * 256 * PZD)         // border half2 count
#define BORDER_BLOCKS ((NBORDER + 255) / 256)           // 1570

// offset shift for the (+1,+1,+1) pad origin
#define PAD_SHIFT (PYD * PZD + PZD + 1)

// ---------------------------------------------------------------------------
// Kernel A (fused): relu_out = max(x+reco,0) ; padded z-pair volume fill ;
// border zeroing folded into trailing blocks. (R11 config — best measured.)
// ---------------------------------------------------------------------------
__global__ void add_relu_pack_kernel(const float* __restrict__ x,
                                     const float* __restrict__ r,
                                     float* __restrict__ relu_out) {
    if (blockIdx.x >= MAIN_BLOCKS) {
        int idx = (blockIdx.x - MAIN_BLOCKS) * blockDim.x + threadIdx.x;
        const int planeA = 3 * PYD * PZD;
        __half2 zero = __floats2half2_rn(0.0f, 0.0f);
        if (idx < planeA) {
            int p = idx / (PYD * PZD);
            int rem = idx - p * (PYD * PZD);
            int xi = (p == 0) ? 0 : (p == 1 ? 257 : 258);
            g_pairP[xi * (PYD * PZD) + rem] = zero;
        } else if (idx < NBORDER) {
            int j = idx - planeA;
            int p = j / (256 * PZD);
            int rem = j - p * (256 * PZD);
            int yi = (p == 0) ? 0 : (p == 1 ? 257 : 258);
            int xi = 1 + rem / PZD;
            int zi = rem - (rem / PZD) * PZD;
            g_pairP[(xi * PYD + yi) * PZD + zi] = zero;
        }
        return;
    }

    int i = blockIdx.x * blockDim.x + threadIdx.x;   // float4 index, 256^3/4 total
    const float4* x4 = (const float4*)x;
    const float4* r4 = (const float4*)r;
    float4 a = x4[i];
    float4 b = r4[i];
    float4 s;
    s.x = a.x + b.x; s.y = a.y + b.y; s.z = a.z + b.z; s.w = a.w + b.w;

    float4 rl;
    rl.x = fmaxf(s.x, 0.0f); rl.y = fmaxf(s.y, 0.0f);
    rl.z = fmaxf(s.z, 0.0f); rl.w = fmaxf(s.w, 0.0f);
    // streaming store: relu output is never re-read; keep L2 for g_pairP
    __stcs((float4*)relu_out + i, rl);

    int base = i * 4;
    int t = i & 63;              // z-chunk index within row (z = 4t)
    int row = i >> 6;            // x*256 + y
    int xi = (row >> 8) + 1;
    int yi = (row & 255) + 1;

    float prev = 0.0f;
    if (t > 0) prev = x[base - 1] + r[base - 1];   // neighbor line: L1/L2 hit

    __half2* rowp = g_pairP + (xi * PYD + yi) * PZD;

    union { __half2 h[4]; uint4 u; } pk;
    pk.h[0] = __floats2half2_rn(prev, s.x);
    pk.h[1] = __floats2half2_rn(s.x, s.y);
    pk.h[2] = __floats2half2_rn(s.y, s.z);
    pk.h[3] = __floats2half2_rn(s.z, s.w);
    ((uint4*)rowp)[t] = pk.u;

    if (t == 63) {
        union { __half2 h[4]; uint4 u; } pk2;
        pk2.h[0] = __floats2half2_rn(s.w, 0.0f);
        pk2.h[1] = __floats2half2_rn(0.0f, 0.0f);
        pk2.h[2] = pk2.h[1];
        pk2.h[3] = pk2.h[1];
        ((uint4*)rowp)[64] = pk2.u;
    }
}

// ---------------------------------------------------------------------------
// half2 SIMD bilinear blend across the 4 corners (z-pair rides in the lanes),
// then fp32 z-lerp.
// ---------------------------------------------------------------------------
__device__ __forceinline__ float tri_blend(__half2 A, __half2 B, __half2 C, __half2 D,
                                           float fx, float fy, float fz) {
    float gx = 1.0f - fx, gy = 1.0f - fy;
    __half2 w00 = __float2half2_rn(gx * gy);
    __half2 w01 = __float2half2_rn(gx * fy);
    __half2 w10 = __float2half2_rn(fx * gy);
    __half2 w11 = __float2half2_rn(fx * fy);
    __half2 P = __hmul2(A, w00);
    P = __hfma2(B, w01, P);
    P = __hfma2(C, w10, P);
    P = __hfma2(D, w11, P);
    float2 p = __half22float2(P);
    return p.x * (1.0f - fz) + p.y * fz;
}

// Single sample (tail); clamp to [-1,256] makes out-of-range exactly 0 via pads
__device__ __forceinline__ float trilin_pad(float px, float py, float pz) {
    px = fminf(fmaxf(px, -1.0f), 256.0f);
    py = fminf(fmaxf(py, -1.0f), 256.0f);
    pz = fminf(fmaxf(pz, -1.0f), 256.0f);
    float xf = floorf(px), yf = floorf(py), zf = floorf(pz);
    float fx = px - xf, fy = py - yf, fz = pz - zf;
    int off = (((int)xf * PYD + (int)yf) * PZD + (int)zf) + PAD_SHIFT;
    const __half2* q = g_pairP + off;
    return tri_blend(__ldg(q), __ldg(q + PZD),
                     __ldg(q + PYD * PZD), __ldg(q + PYD * PZD + PZD),
                     fx, fy, fz);
}

__device__ __forceinline__ void slab_clip(float p0, float dd, float lo, float hi,
                                          float& t0, float& t1) {
    if (fabsf(dd) > 1e-9f) {
        float r = 1.0f / dd;
        float ta = (lo - p0) * r, tb = (hi - p0) * r;
        t0 = fmaxf(t0, fminf(ta, tb));
        t1 = fminf(t1, fmaxf(ta, tb));
    } else if (p0 <= lo || p0 >= hi) {
        t1 = -1e9f;
    }
}

// ---------------------------------------------------------------------------
// Kernel B: cone-beam forward projection — single-wave, full ray per thread.
// 6 samples per iteration, 24 loads in flight. Grid-limited at 6.92 CTAs/SM,
// so __launch_bounds__(128,7) (<=73 regs) costs zero occupancy.
// ---------------------------------------------------------------------------
__global__ void __launch_bounds__(128, 7)
proj_kernel(const float* __restrict__ src_pos,
            const float* __restrict__ det_center,
            const float* __restrict__ det_u_vec,
            const float* __restrict__ det_v_vec,
            const float* __restrict__ pdu,
            const float* __restrict__ pdv,
            const float* __restrict__ psp,
            float* __restrict__ sino) {
    const int v = threadIdx.x;
    const int u = blockIdx.x;
    const int view = blockIdx.y;

    const float du = __ldg(pdu);
    const float dv = __ldg(pdv);
    const float inv_sp = 1.0f / __ldg(psp);

    const float sx = __ldg(&src_pos[view * 3 + 0]);
    const float sy = __ldg(&src_pos[view * 3 + 1]);
    const float sz = __ldg(&src_pos[view * 3 + 2]);
    const float ccx = __ldg(&det_center[view * 3 + 0]);
    const float ccy = __ldg(&det_center[view * 3 + 1]);
    const float ccz = __ldg(&det_center[view * 3 + 2]);
    const float ux = __ldg(&det_u_vec[view * 3 + 0]);
    const float uy = __ldg(&det_u_vec[view * 3 + 1]);
    const float uz = __ldg(&det_u_vec[view * 3 + 2]);
    const float vx = __ldg(&det_v_vec[view * 3 + 0]);
    const float vy = __ldg(&det_v_vec[view * 3 + 1]);
    const float vz = __ldg(&det_v_vec[view * 3 + 2]);

    const float uu = ((float)u - (float)(DETU - 1) * 0.5f) * du;
    const float vv = ((float)v - (float)(DETV - 1) * 0.5f) * dv;

    const float dx = (ccx + uu * ux + vv * vx) - sx;
    const float dy = (ccy + uu * uy + vv * vy) - sy;
    const float dz = (ccz + uu * uz + vv * vz) - sz;
    const float ray_len = sqrtf(dx * dx + dy * dy + dz * dz);

    const float cx = (float)(NX - 1) * 0.5f;
    const float cy = (float)(NY - 1) * 0.5f;
    const float cz = (float)(NZ - 1) * 0.5f;
    const float p0x = fmaf(sx, inv_sp, cx);
    const float p0y = fmaf(sy, inv_sp, cy);
    const float p0z = fmaf(sz, inv_sp, cz);
    const float ddx = dx * inv_sp;
    const float ddy = dy * inv_sp;
    const float ddz = dz * inv_sp;

    // outer clip: beyond (-1, N) in any dim contributes exactly 0 (zero pads)
    float t0 = 0.0f, t1 = 1.0f;
    slab_clip(p0x, ddx, -1.0f, (float)NX, t0, t1);
    slab_clip(p0y, ddy, -1.0f, (float)NY, t0, t1);
    slab_clip(p0z, ddz, -1.0f, (float)NZ, t0, t1);

    int k0 = 0, k1 = -1;
    if (t1 > t0) {
        k0 = max((int)ceilf(t0 * (float)NSTEPS - 0.5f) - 1, 0);
        k1 = min((int)floorf(t1 * (float)NSTEPS - 0.5f) + 1, NSTEPS - 1);
    }

    const float inv_n = 1.0f / (float)NSTEPS;
    const float ddnx = ddx * inv_n, ddny = ddy * inv_n, ddnz = ddz * inv_n;
    const float bx = fmaf(0.5f, ddnx, p0x);
    const float by = fmaf(0.5f, ddny, p0y);
    const float bz = fmaf(0.5f, ddnz, p0z);

    float acc = 0.0f;
    int kk = k0;

#define PREP(i, KF)                                                            \
    float px##i = fminf(fmaxf(fmaf((KF), ddnx, bx), -1.0f), 256.0f);           \
    float py##i = fminf(fmaxf(fmaf((KF), ddny, by), -1.0f), 256.0f);           \
    float pz##i = fminf(fmaxf(fmaf((KF), ddnz, bz), -1.0f), 256.0f);           \
    float xf##i = floorf(px##i), yf##i = floorf(py##i), zf##i = floorf(pz##i); \
    float fx##i = px##i - xf##i, fy##i = py##i - yf##i, fz##i = pz##i - zf##i; \
    int off##i = (((int)xf##i * PYD + (int)yf##i) * PZD + (int)zf##i) + PAD_SHIFT;

#define LOADS(i)                                                               \
    __half2 A##i = __ldg(g_pairP + off##i);                                    \
    __half2 B##i = __ldg(g_pairP + off##i + PZD);                              \
    __half2 C##i = __ldg(g_pairP + off##i + PYD * PZD);                        \
    __half2 D##i = __ldg(g_pairP + off##i + PYD * PZD + PZD);

    // 6 samples per iteration, 24 loads batched before consumption (MLP)
    for (; kk + 5 <= k1; kk += 6) {
        PREP(0, (float)kk)
        PREP(1, (float)(kk + 1))
        PREP(2, (float)(kk + 2))
        PREP(3, (float)(kk + 3))
        PREP(4, (float)(kk + 4))
        PREP(5, (float)(kk + 5))

        LOADS(0) LOADS(1) LOADS(2) LOADS(3) LOADS(4) LOADS(5)

        acc += tri_blend(A0, B0, C0, D0, fx0, fy0, fz0);
        acc += tri_blend(A1, B1, C1, D1, fx1, fy1, fz1);
        acc += tri_blend(A2, B2, C2, D2, fx2, fy2, fz2);
        acc += tri_blend(A3, B3, C3, D3, fx3, fy3, fz3);
        acc += tri_blend(A4, B4, C4, D4, fx4, fy4, fz4);
        acc += tri_blend(A5, B5, C5, D5, fx5, fy5, fz5);
    }
    for (; kk <= k1; ++kk) {
        float kf = (float)kk;
        acc += trilin_pad(fmaf(kf, ddnx, bx), fmaf(kf, ddny, by), fmaf(kf, ddnz, bz));
    }
#undef PREP
#undef LOADS

    sino[(view * DETU + u) * DETV + v] = acc * (ray_len * inv_n);
}

// ---------------------------------------------------------------------------
// Launch (single stream, two kernels — overlap attempts measured worse)
// ---------------------------------------------------------------------------
extern "C" void kernel_launch(void* const* d_in, const int* in_sizes, int n_in,
                              void* d_out, int out_size) {
    const float* x    = (const float*)d_in[0];
    const float* reco = (const float*)d_in[1];
    const float* src  = (const float*)d_in[2];
    const float* dc   = (const float*)d_in[3];
    const float* duv  = (const float*)d_in[4];
    const float* dvv  = (const float*)d_in[5];
    const float* pdu  = (const float*)d_in[6];
    const float* pdv  = (const float*)d_in[7];
    const float* psp  = (const float*)d_in[8];

    float* out  = (float*)d_out;
    float* sino = out;                                   // [8,128,128]
    float* relu = out + NVIEWS * DETU * DETV;            // [256^3]

    // fused: main blocks do add/relu/pack, trailing blocks zero pad borders
    add_relu_pack_kernel<<<MAIN_BLOCKS + BORDER_BLOCKS, 256>>>(x, reco, relu);

    dim3 grid(DETU, NVIEWS);
    proj_kernel<<<grid, 128>>>(src, dc, duv, dvv, pdu, pdv, psp, sino);
}